// round 2
// baseline (speedup 1.0000x reference)
#include <cuda_runtime.h>

#define Bb 4
#define Ss 4096
#define Ee 256
#define Hh 64

// Scratch for projected Q, K, V (device globals: no allocation allowed)
__device__ float g_q[Bb * Ss * Hh];
__device__ float g_k[Bb * Ss * Hh];
__device__ float g_v[Bb * Ss * Hh];

typedef unsigned long long ull;

__device__ __forceinline__ ull ffma2(ull a, ull b, ull c) {
    ull d;
    asm("fma.rn.f32x2 %0, %1, %2, %3;" : "=l"(d) : "l"(a), "l"(b), "l"(c));
    return d;
}
__device__ __forceinline__ ull fmul2(ull a, ull b) {
    ull d;
    asm("mul.rn.f32x2 %0, %1, %2;" : "=l"(d) : "l"(a), "l"(b));
    return d;
}
__device__ __forceinline__ ull pack2(float lo, float hi) {
    ull d;
    asm("mov.b64 %0, {%1, %2};" : "=l"(d) : "f"(lo), "f"(hi));
    return d;
}
__device__ __forceinline__ void unpack2(ull v, float& lo, float& hi) {
    asm("mov.b64 {%0, %1}, %2;" : "=f"(lo), "=f"(hi) : "l"(v));
}
__device__ __forceinline__ float fast_exp2(float x) {
    float y;
    asm("ex2.approx.ftz.f32 %0, %1;" : "=f"(y) : "f"(x));
    return y;
}

// ---------------------------------------------------------------------------
// Projection: [B*S, 256] @ [256, 64] x3 -> g_q, g_k, g_v
// 512 blocks x 192 threads. Each block: 32 rows of x in smem.
// Thread t owns one output column: t<64 -> Q col t, t<128 -> K, else V.
// Weight loads are coalesced across threads (fixed k, h varies); x reads are
// warp-broadcast LDS.128.
// ---------------------------------------------------------------------------
__global__ __launch_bounds__(192) void proj_kernel(
    const float* __restrict__ x,
    const float* __restrict__ wk,
    const float* __restrict__ wq,
    const float* __restrict__ wv)
{
    __shared__ __align__(16) float xs[32 * Ee];
    const int row0 = blockIdx.x * 32;
    const int t = threadIdx.x;

    const float4* xg = (const float4*)(x + (size_t)row0 * Ee);
    float4* xs4 = (float4*)xs;
    for (int i = t; i < 32 * (Ee / 4); i += 192) xs4[i] = xg[i];
    __syncthreads();

    const int h = t & 63;
    const float* W = (t < 64) ? wq : (t < 128) ? wk : wv;
    float* G = (t < 64) ? g_q : (t < 128) ? g_k : g_v;

    float acc[32];
#pragma unroll
    for (int r = 0; r < 32; r++) acc[r] = 0.f;

    for (int k = 0; k < Ee; k += 4) {
        float w0 = W[(k + 0) * Hh + h];
        float w1 = W[(k + 1) * Hh + h];
        float w2 = W[(k + 2) * Hh + h];
        float w3 = W[(k + 3) * Hh + h];
#pragma unroll
        for (int r = 0; r < 32; r++) {
            float4 xv = xs4[r * (Ee / 4) + (k >> 2)];
            acc[r] = fmaf(xv.x, w0, acc[r]);
            acc[r] = fmaf(xv.y, w1, acc[r]);
            acc[r] = fmaf(xv.z, w2, acc[r]);
            acc[r] = fmaf(xv.w, w3, acc[r]);
        }
    }
#pragma unroll
    for (int r = 0; r < 32; r++) G[(size_t)(row0 + r) * Hh + h] = acc[r];
}

// ---------------------------------------------------------------------------
// Flash attention, fp32 with packed f32x2 FMA.
// Grid: (S/128, B). Block: 128 threads; thread = one query row.
// q (scaled by n_emb^-0.5 * log2e) and O accumulator live in registers as
// f32x2 pairs. K/V tiles (16 rows x 64) double-buffered in smem; one
// __syncthreads per tile. Online softmax in exp2 domain.
// ---------------------------------------------------------------------------
#define KT 16

__global__ __launch_bounds__(128, 1) void flash_kernel(float* __restrict__ out)
{
    __shared__ __align__(16) float sK[2][KT * Hh];
    __shared__ __align__(16) float sV[2][KT * Hh];

    const int b = blockIdx.y;
    const int qrow = blockIdx.x * 128 + threadIdx.x;
    const int t = threadIdx.x;

    const float* qg = g_q + ((size_t)b * Ss + qrow) * Hh;
    const float4* kg4 = (const float4*)(g_k + (size_t)b * Ss * Hh);
    const float4* vg4 = (const float4*)(g_v + (size_t)b * Ss * Hh);

    // fold scale (n_emb^-0.5 = 1/16) and log2(e) into q
    const float qscale = 0.0625f * 1.4426950408889634f;

    ull q2[32];
#pragma unroll
    for (int i = 0; i < 16; i++) {
        float4 v = ((const float4*)qg)[i];
        q2[2 * i + 0] = pack2(v.x * qscale, v.y * qscale);
        q2[2 * i + 1] = pack2(v.z * qscale, v.w * qscale);
    }

    ull o2[32];
#pragma unroll
    for (int i = 0; i < 32; i++) o2[i] = 0ULL;

    float m = -1e30f;
    float l = 0.f;

    // preload tile 0: KT*Hh = 1024 floats = 256 float4; 2 per thread per tensor
    float4 rk0 = kg4[t];
    float4 rk1 = kg4[128 + t];
    float4 rv0 = vg4[t];
    float4 rv1 = vg4[128 + t];
    ((float4*)sK[0])[t] = rk0;
    ((float4*)sK[0])[128 + t] = rk1;
    ((float4*)sV[0])[t] = rv0;
    ((float4*)sV[0])[128 + t] = rv1;
    __syncthreads();

    const int NT = Ss / KT;  // 256
    for (int tile = 0; tile < NT; tile++) {
        const int cur = tile & 1;
        const int nxt = cur ^ 1;

        // prefetch next tile into registers (hidden under compute)
        if (tile + 1 < NT) {
            const float4* kn = kg4 + (tile + 1) * (KT * Hh / 4);
            const float4* vn = vg4 + (tile + 1) * (KT * Hh / 4);
            rk0 = kn[t];
            rk1 = kn[128 + t];
            rv0 = vn[t];
            rv1 = vn[128 + t];
        }

        // ---- scores: s[j] = q . K[j]  (already in log2 domain) ----
        float s[KT];
#pragma unroll 4
        for (int j = 0; j < KT; j++) {
            const ulonglong2* Kr = (const ulonglong2*)(sK[cur] + j * Hh);
            ull a0 = 0ULL, a1 = 0ULL;
#pragma unroll
            for (int d = 0; d < 16; d++) {
                ulonglong2 kk = Kr[d];
                a0 = ffma2(q2[2 * d + 0], kk.x, a0);
                a1 = ffma2(q2[2 * d + 1], kk.y, a1);
            }
            float x0, x1, y0, y1;
            unpack2(a0, x0, x1);
            unpack2(a1, y0, y1);
            s[j] = (x0 + x1) + (y0 + y1);
        }

        // ---- online softmax update ----
        float mt = m;
#pragma unroll
        for (int j = 0; j < KT; j++) mt = fmaxf(mt, s[j]);
        float corr = fast_exp2(m - mt);
        m = mt;
        l *= corr;
        ull corr2 = pack2(corr, corr);
#pragma unroll
        for (int i = 0; i < 32; i++) o2[i] = fmul2(o2[i], corr2);

        // ---- accumulate P @ V ----
#pragma unroll 4
        for (int j = 0; j < KT; j++) {
            float p = fast_exp2(s[j] - m);
            l += p;
            ull p2 = pack2(p, p);
            const ulonglong2* Vr = (const ulonglong2*)(sV[cur] + j * Hh);
#pragma unroll
            for (int d = 0; d < 16; d++) {
                ulonglong2 vv = Vr[d];
                o2[2 * d + 0] = ffma2(p2, vv.x, o2[2 * d + 0]);
                o2[2 * d + 1] = ffma2(p2, vv.y, o2[2 * d + 1]);
            }
        }

        // publish prefetched tile
        if (tile + 1 < NT) {
            ((float4*)sK[nxt])[t] = rk0;
            ((float4*)sK[nxt])[128 + t] = rk1;
            ((float4*)sV[nxt])[t] = rv0;
            ((float4*)sV[nxt])[128 + t] = rv1;
        }
        __syncthreads();
    }

    // ---- epilogue: O / l ----
    float inv = 1.f / l;
    float4* og = (float4*)(out + ((size_t)b * Ss + qrow) * Hh);
#pragma unroll
    for (int i = 0; i < 16; i++) {
        float x0, x1, y0, y1;
        unpack2(o2[2 * i + 0], x0, x1);
        unpack2(o2[2 * i + 1], y0, y1);
        float4 v;
        v.x = x0 * inv;
        v.y = x1 * inv;
        v.z = y0 * inv;
        v.w = y1 * inv;
        og[i] = v;
    }
}

extern "C" void kernel_launch(void* const* d_in, const int* in_sizes, int n_in,
                              void* d_out, int out_size)
{
    const float* ini_emb = (const float*)d_in[0];
    const float* wk = (const float*)d_in[1];
    const float* wq = (const float*)d_in[2];
    const float* wv = (const float*)d_in[3];
    float* out = (float*)d_out;

    proj_kernel<<<(Bb * Ss) / 32, 192>>>(ini_emb, wk, wq, wv);
    flash_kernel<<<dim3(Ss / 128, Bb), 128>>>(out);
}